// round 1
// baseline (speedup 1.0000x reference)
#include <cuda_runtime.h>
#include <cuda_bf16.h>
#include <math.h>

// Problem constants
#define Bn 4
#define Npts 120000
#define TOTAL_PTS (Bn * Npts)   // 480000
#define FEAT 128
#define Hg 128
#define Wg 128
#define EPSF 1e-5f

// Folded weights (BN fused into linear): device globals (no allocs allowed)
__device__ float d_W1f[64 * 4];
__device__ float d_b1f[64];
__device__ float d_W2t[64 * 128];   // TRANSPOSED: [k][o]
__device__ float d_b2f[128];
__device__ float d_W3f[128 * 128];  // row-major [o][k]
__device__ float d_b3f[128];

__global__ void prep_kernel(
    const float* __restrict__ W1, const float* __restrict__ b1,
    const float* __restrict__ g1, const float* __restrict__ be1,
    const float* __restrict__ m1, const float* __restrict__ v1,
    const float* __restrict__ W2, const float* __restrict__ b2,
    const float* __restrict__ g2, const float* __restrict__ be2,
    const float* __restrict__ m2, const float* __restrict__ v2,
    const float* __restrict__ W3, const float* __restrict__ b3,
    const float* __restrict__ g3, const float* __restrict__ be3,
    const float* __restrict__ m3, const float* __restrict__ v3)
{
    int t = threadIdx.x;
    for (int o = t; o < 64; o += blockDim.x) {
        float s = g1[o] * rsqrtf(v1[o] + EPSF);
        d_b1f[o] = (b1[o] - m1[o]) * s + be1[o];
        #pragma unroll
        for (int i = 0; i < 4; i++) d_W1f[o * 4 + i] = W1[o * 4 + i] * s;
    }
    for (int o = t; o < 128; o += blockDim.x) {
        float s = g2[o] * rsqrtf(v2[o] + EPSF);
        d_b2f[o] = (b2[o] - m2[o]) * s + be2[o];
        for (int k = 0; k < 64; k++) d_W2t[k * 128 + o] = W2[o * 64 + k] * s;
    }
    for (int o = t; o < 128; o += blockDim.x) {
        float s = g3[o] * rsqrtf(v3[o] + EPSF);
        d_b3f[o] = (b3[o] - m3[o]) * s + be3[o];
        for (int k = 0; k < 128; k++) d_W3f[o * 128 + k] = W3[o * 128 + k] * s;
    }
}

// Shared memory layout (floats):
// sW1[256] | sW2t[8192] | sW3[16384] | sb1[64] | sb2[128] | sb3[128]
#define SM_W1  0
#define SM_W2T 256
#define SM_W3  (256 + 8192)
#define SM_B1  (256 + 8192 + 16384)
#define SM_B2  (SM_B1 + 64)
#define SM_B3  (SM_B2 + 128)
#define SM_TOTAL (SM_B3 + 128)           // 25152 floats
#define SMEM_BYTES (SM_TOTAL * 4)        // 100608 B

#define TPB 128

__global__ void __launch_bounds__(TPB, 2)
lidar_encoder_kernel(const float4* __restrict__ pts, float* __restrict__ out)
{
    extern __shared__ float sm[];
    // stage all weights into shared (broadcast-read later)
    for (int i = threadIdx.x; i < 256; i += TPB)   sm[SM_W1 + i]  = d_W1f[i];
    for (int i = threadIdx.x; i < 8192; i += TPB)  sm[SM_W2T + i] = d_W2t[i];
    for (int i = threadIdx.x; i < 16384; i += TPB) sm[SM_W3 + i]  = d_W3f[i];
    for (int i = threadIdx.x; i < 64; i += TPB)    sm[SM_B1 + i]  = d_b1f[i];
    for (int i = threadIdx.x; i < 128; i += TPB)   sm[SM_B2 + i]  = d_b2f[i];
    for (int i = threadIdx.x; i < 128; i += TPB)   sm[SM_B3 + i]  = d_b3f[i];
    __syncthreads();

    const float* sW1  = &sm[SM_W1];
    const float* sW2t = &sm[SM_W2T];
    const float* sW3  = &sm[SM_W3];
    const float* sb1  = &sm[SM_B1];
    const float* sb2  = &sm[SM_B2];
    const float* sb3  = &sm[SM_B3];
    int* iout = (int*)out;

    for (int p0 = blockIdx.x * TPB; p0 < TOTAL_PTS; p0 += gridDim.x * TPB) {
        int p = p0 + threadIdx.x;
        if (p >= TOTAL_PTS) continue;
        float4 pt = pts[p];

        // validity + grid cell (must match reference fp32 semantics)
        float xn = (pt.x + 50.0f) / 100.0f;
        float yn = (pt.y + 50.0f) / 100.0f;
        bool valid = (xn >= 0.0f) && (xn <= 1.0f) && (yn >= 0.0f) && (yn <= 1.0f);
        if (!valid) continue;

        int gx = (int)(xn * 127.0f);
        int gy = (int)(yn * 127.0f);
        gx = min(max(gx, 0), 127);
        gy = min(max(gy, 0), 127);
        int b = p / Npts;
        int base = b * (FEAT * Hg * Wg) + gy * Wg + gx;

        // ---- layer 1: 4 -> 64 (h1 lives in local mem; L1-resident) ----
        float h1[64];
        #pragma unroll 8
        for (int o = 0; o < 64; o++) {
            const float4 w = *(const float4*)&sW1[o * 4];
            float a = sb1[o];
            a = fmaf(pt.x, w.x, a);
            a = fmaf(pt.y, w.y, a);
            a = fmaf(pt.z, w.z, a);
            a = fmaf(pt.w, w.w, a);
            h1[o] = fmaxf(a, 0.0f);
        }

        // ---- layer 2: 64 -> 128 (h2 in registers; k rolled, o fully unrolled) ----
        float h2[128];
        #pragma unroll
        for (int o = 0; o < 128; o++) h2[o] = sb2[o];

        for (int k = 0; k < 64; k++) {
            float a = h1[k];
            const float* w = &sW2t[k * 128];
            #pragma unroll
            for (int o = 0; o < 128; o += 4) {
                const float4 wv = *(const float4*)(w + o);
                h2[o]     = fmaf(a, wv.x, h2[o]);
                h2[o + 1] = fmaf(a, wv.y, h2[o + 1]);
                h2[o + 2] = fmaf(a, wv.z, h2[o + 2]);
                h2[o + 3] = fmaf(a, wv.w, h2[o + 3]);
            }
        }
        #pragma unroll
        for (int o = 0; o < 128; o++) h2[o] = fmaxf(h2[o], 0.0f);

        // ---- layer 3: 128 -> 128, fused BN+ReLU + scatter-max ----
        for (int o = 0; o < 128; o++) {
            const float4* w = (const float4*)&sW3[o * 128];
            float a0 = sb3[o], a1 = 0.0f, a2 = 0.0f, a3 = 0.0f;
            #pragma unroll
            for (int k = 0; k < 32; k++) {
                const float4 wv = w[k];
                a0 = fmaf(h2[4 * k],     wv.x, a0);
                a1 = fmaf(h2[4 * k + 1], wv.y, a1);
                a2 = fmaf(h2[4 * k + 2], wv.z, a2);
                a3 = fmaf(h2[4 * k + 3], wv.w, a3);
            }
            float r = fmaxf((a0 + a1) + (a2 + a3), 0.0f);
            // all values >= 0 -> int-bitcast atomicMax == float max; 0-init matches
            // the reference's neginf->0 rule.
            atomicMax(&iout[base + o * (Hg * Wg)], __float_as_int(r));
        }
    }
}

extern "C" void kernel_launch(void* const* d_in, const int* in_sizes, int n_in,
                              void* d_out, int out_size)
{
    const float* points = (const float*)d_in[0];
    const float* W1  = (const float*)d_in[1];
    const float* b1  = (const float*)d_in[2];
    const float* g1  = (const float*)d_in[3];
    const float* be1 = (const float*)d_in[4];
    const float* m1  = (const float*)d_in[5];
    const float* v1  = (const float*)d_in[6];
    const float* W2  = (const float*)d_in[7];
    const float* b2  = (const float*)d_in[8];
    const float* g2  = (const float*)d_in[9];
    const float* be2 = (const float*)d_in[10];
    const float* m2  = (const float*)d_in[11];
    const float* v2  = (const float*)d_in[12];
    const float* W3  = (const float*)d_in[13];
    const float* b3  = (const float*)d_in[14];
    const float* g3  = (const float*)d_in[15];
    const float* be3 = (const float*)d_in[16];
    const float* m3  = (const float*)d_in[17];
    const float* v3  = (const float*)d_in[18];

    // zero-init output (graph-capturable)
    cudaMemsetAsync(d_out, 0, (size_t)out_size * sizeof(float), 0);

    prep_kernel<<<1, 256>>>(W1, b1, g1, be1, m1, v1,
                            W2, b2, g2, be2, m2, v2,
                            W3, b3, g3, be3, m3, v3);

    static bool attr_set = false;
    // idempotent; safe to call on every launch
    cudaFuncSetAttribute(lidar_encoder_kernel,
                         cudaFuncAttributeMaxDynamicSharedMemorySize, SMEM_BYTES);
    (void)attr_set;

    lidar_encoder_kernel<<<296, TPB, SMEM_BYTES>>>((const float4*)points, (float*)d_out);
}

// round 3
// speedup vs baseline: 2.1880x; 2.1880x over previous
#include <cuda_runtime.h>
#include <cuda_fp16.h>
#include <cstdint>

#define TOTAL_PTS 480000
#define NWTILES   15000        // 480000 / 32 points per warp-tile
#define HW        16384        // 128*128
#define EPSF      1e-5f
#define STR2      72           // K=64  + 8 halfs pad
#define STR3      136          // K=128 + 8 halfs pad

// ---------------- warp MMA helpers (sm_80+; safe on sm_103 base target) -------
__device__ __forceinline__ uint32_t smem_u32(const void* p){
    uint32_t a;
    asm("{ .reg .u64 t; cvta.to.shared.u64 t, %1; cvt.u32.u64 %0, t; }" : "=r"(a) : "l"(p));
    return a;
}
__device__ __forceinline__ void ldsm4(uint32_t r[4], uint32_t addr){
    asm volatile("ldmatrix.sync.aligned.m8n8.x4.shared.b16 {%0,%1,%2,%3}, [%4];"
        : "=r"(r[0]), "=r"(r[1]), "=r"(r[2]), "=r"(r[3]) : "r"(addr));
}
__device__ __forceinline__ void mma16816(float d[4], const uint32_t a[4], uint32_t b0, uint32_t b1){
    asm volatile("mma.sync.aligned.m16n8k16.row.col.f32.f16.f16.f32 "
        "{%0,%1,%2,%3},{%4,%5,%6,%7},{%8,%9},{%0,%1,%2,%3};"
        : "+f"(d[0]), "+f"(d[1]), "+f"(d[2]), "+f"(d[3])
        : "r"(a[0]), "r"(a[1]), "r"(a[2]), "r"(a[3]), "r"(b0), "r"(b1));
}
__device__ __forceinline__ uint32_t pack2(float a, float b){
    __half2 h = __floats2half2_rn(a, b);
    return *reinterpret_cast<uint32_t*>(&h);
}

// ---------------- prepped globals (BN folded, hi/lo split, padded layout) -----
__device__ __align__(16) unsigned short g_w2hi[128*STR2];
__device__ __align__(16) unsigned short g_w2lo[128*STR2];
__device__ __align__(16) unsigned short g_w3hi[128*STR3];
__device__ __align__(16) unsigned short g_w3lo[128*STR3];
__device__ __align__(16) float g_w1f[256];
__device__ float g_b1f[64], g_b2f[128], g_b3f[128];

__global__ void prep_kernel(
    const float* __restrict__ W1, const float* __restrict__ b1,
    const float* __restrict__ g1, const float* __restrict__ be1,
    const float* __restrict__ m1, const float* __restrict__ v1,
    const float* __restrict__ W2, const float* __restrict__ b2,
    const float* __restrict__ g2, const float* __restrict__ be2,
    const float* __restrict__ m2, const float* __restrict__ v2,
    const float* __restrict__ W3, const float* __restrict__ b3,
    const float* __restrict__ g3, const float* __restrict__ be3,
    const float* __restrict__ m3, const float* __restrict__ v3)
{
    int idx = blockIdx.x * blockDim.x + threadIdx.x;
    int nthr = gridDim.x * blockDim.x;
    for (int i = idx; i < 8192; i += nthr) {           // W2 [128 n][64 k]
        int o = i >> 6, k = i & 63;
        float s = g2[o] * rsqrtf(v2[o] + EPSF);
        float w = W2[i] * s;
        float hi = __half2float(__float2half_rn(w));
        g_w2hi[o*STR2 + k] = __half_as_ushort(__float2half_rn(w));
        g_w2lo[o*STR2 + k] = __half_as_ushort(__float2half_rn(w - hi));
    }
    for (int i = idx; i < 16384; i += nthr) {          // W3 [128 n][128 k]
        int o = i >> 7, k = i & 127;
        float s = g3[o] * rsqrtf(v3[o] + EPSF);
        float w = W3[i] * s;
        float hi = __half2float(__float2half_rn(w));
        g_w3hi[o*STR3 + k] = __half_as_ushort(__float2half_rn(w));
        g_w3lo[o*STR3 + k] = __half_as_ushort(__float2half_rn(w - hi));
    }
    for (int i = idx; i < 256; i += nthr) { int o = i >> 2; g_w1f[i] = W1[i] * g1[o] * rsqrtf(v1[o] + EPSF); }
    for (int i = idx; i < 64; i += nthr)  { float s = g1[i]*rsqrtf(v1[i]+EPSF); g_b1f[i] = (b1[i]-m1[i])*s + be1[i]; }
    for (int i = idx; i < 128; i += nthr) { float s = g2[i]*rsqrtf(v2[i]+EPSF); g_b2f[i] = (b2[i]-m2[i])*s + be2[i]; }
    for (int i = idx; i < 128; i += nthr) { float s = g3[i]*rsqrtf(v3[i]+EPSF); g_b3f[i] = (b3[i]-m3[i])*s + be3[i]; }
}

// ---------------- smem layout (bytes) ----------------
#define OFF_W2H  0
#define OFF_W2L  (OFF_W2H + 128*STR2*2)     // 18432
#define OFF_W3H  (OFF_W2L + 128*STR2*2)     // 36864
#define OFF_W3L  (OFF_W3H + 128*STR3*2)     // 71680
#define OFF_A1H  (OFF_W3L + 128*STR3*2)     // 106496
#define OFF_A1L  (OFF_A1H + 128*STR2*2)     // 124928
#define OFF_A2H  (OFF_A1L + 128*STR2*2)     // 143360
#define OFF_A2L  (OFF_A2H + 128*STR3*2)     // 178176
#define OFF_B1   (OFF_A2L + 128*STR3*2)     // 212992
#define OFF_B2   (OFF_B1 + 256)
#define OFF_B3   (OFF_B2 + 512)
#define OFF_W1   (OFF_B3 + 512)
#define SMEM_SZ  (OFF_W1 + 1024)            // 215296

// 3-pass hi/lo warp GEMM over one 64-col n-half. acc[mb][nt][4].
template<int KST, int STRIDE>
__device__ __forceinline__ void warp_gemm(uint32_t aHi, uint32_t aLo,
                                          uint32_t bHi, uint32_t bLo,
                                          int lane, float acc[2][8][4])
{
    const uint32_t aoff = ((lane & 15) * STRIDE + ((lane >> 4) << 3)) * 2;
    const uint32_t boff = (((lane & 7) + ((lane >> 4) << 3)) * STRIDE) * 2 + (lane & 8) * 2;
    #pragma unroll
    for (int pass = 0; pass < 3; pass++) {
        const uint32_t A = (pass == 1) ? aLo : aHi;
        const uint32_t B = (pass == 2) ? bLo : bHi;
        #pragma unroll
        for (int ks = 0; ks < KST; ks++) {
            uint32_t a0[4], a1[4];
            ldsm4(a0, A + aoff + ks * 32);
            ldsm4(a1, A + aoff + ks * 32 + 16 * STRIDE * 2);
            #pragma unroll
            for (int ntp = 0; ntp < 4; ntp++) {
                uint32_t b[4];
                ldsm4(b, B + boff + ks * 32 + ntp * 16 * STRIDE * 2);
                mma16816(acc[0][2*ntp],     a0, b[0], b[1]);
                mma16816(acc[0][2*ntp + 1], a0, b[2], b[3]);
                mma16816(acc[1][2*ntp],     a1, b[0], b[1]);
                mma16816(acc[1][2*ntp + 1], a1, b[2], b[3]);
            }
        }
    }
}

__global__ void __launch_bounds__(128, 1)
enc_kernel(const float4* __restrict__ pts, float* __restrict__ out)
{
    extern __shared__ __align__(16) char sm[];
    const uint32_t smb = smem_u32(sm);
    const int t = threadIdx.x, lane = t & 31, wid = t >> 5;
    int* iout = (int*)out;

    { // stage weights
        uint4* d; const uint4* s;
        d = (uint4*)(sm + OFF_W2H); s = (const uint4*)g_w2hi; for (int i = t; i < 128*STR2*2/16; i += 128) d[i] = s[i];
        d = (uint4*)(sm + OFF_W2L); s = (const uint4*)g_w2lo; for (int i = t; i < 128*STR2*2/16; i += 128) d[i] = s[i];
        d = (uint4*)(sm + OFF_W3H); s = (const uint4*)g_w3hi; for (int i = t; i < 128*STR3*2/16; i += 128) d[i] = s[i];
        d = (uint4*)(sm + OFF_W3L); s = (const uint4*)g_w3lo; for (int i = t; i < 128*STR3*2/16; i += 128) d[i] = s[i];
        float* f;
        f = (float*)(sm + OFF_W1); for (int i = t; i < 256; i += 128) f[i] = g_w1f[i];
        f = (float*)(sm + OFF_B1); if (t < 64)  f[t] = g_b1f[t];
        f = (float*)(sm + OFF_B2); if (t < 128) f[t] = g_b2f[t];
        f = (float*)(sm + OFF_B3); if (t < 128) f[t] = g_b3f[t];
    }
    __syncthreads();

    const float4* sW1 = (const float4*)(sm + OFF_W1);
    const float* sb1 = (const float*)(sm + OFF_B1);
    const float* sb2 = (const float*)(sm + OFF_B2);
    const float* sb3 = (const float*)(sm + OFF_B3);

    const int wrow0 = wid * 32;                        // this warp's 32-row strip
    const uint32_t a1H = smb + OFF_A1H + wrow0 * STR2 * 2;
    const uint32_t a1L = smb + OFF_A1L + wrow0 * STR2 * 2;
    const uint32_t a2H = smb + OFF_A2H + wrow0 * STR3 * 2;
    const uint32_t a2L = smb + OFF_A2L + wrow0 * STR3 * 2;

    const int gwarp = blockIdx.x * 4 + wid;
    const int nwarps = gridDim.x * 4;

    for (int wt = gwarp; wt < NWTILES; wt += nwarps) {
        const int p = wt * 32 + lane;
        float4 pt = pts[p];

        float xn = (pt.x + 50.0f) / 100.0f;
        float yn = (pt.y + 50.0f) / 100.0f;
        bool valid = (xn >= 0.0f) && (xn <= 1.0f) && (yn >= 0.0f) && (yn <= 1.0f);
        int gx = min(max((int)(xn * 127.0f), 0), 127);
        int gy = min(max((int)(yn * 127.0f), 0), 127);
        int base = valid ? ((p / 120000) * (128 * HW) + gy * 128 + gx) : -1;

        // ---- layer 1 (fp32 SIMT) + hi/lo pack into A1 row (wrow0+lane) ----
        {
            float h1[64];
            #pragma unroll
            for (int o = 0; o < 64; o++) {
                float4 w = sW1[o];
                float a = sb1[o];
                a = fmaf(pt.x, w.x, a); a = fmaf(pt.y, w.y, a);
                a = fmaf(pt.z, w.z, a); a = fmaf(pt.w, w.w, a);
                h1[o] = fmaxf(a, 0.0f);
            }
            uint32_t rowb = (uint32_t)(lane * STR2 * 2);
            #pragma unroll
            for (int k = 0; k < 64; k += 4) {
                float v0 = h1[k], v1 = h1[k+1], v2 = h1[k+2], v3 = h1[k+3];
                float h0 = __half2float(__float2half_rn(v0));
                float hh1 = __half2float(__float2half_rn(v1));
                float h2 = __half2float(__float2half_rn(v2));
                float h3 = __half2float(__float2half_rn(v3));
                uint2 hi = make_uint2(pack2(v0, v1), pack2(v2, v3));
                uint2 lo = make_uint2(pack2(v0 - h0, v1 - hh1), pack2(v2 - h2, v3 - h3));
                *(uint2*)(sm + (a1H - smb) + rowb + k * 2) = hi;
                *(uint2*)(sm + (a1L - smb) + rowb + k * 2) = lo;
            }
        }
        __syncwarp();

        const int g = lane >> 2;
        const int cbase = (lane & 3) * 2;

        // ---- layer 2: [32 x 64] x [64 x 128]^T, per n-half ----
        #pragma unroll
        for (int nh = 0; nh < 2; nh++) {
            float acc[2][8][4];
            #pragma unroll
            for (int mb = 0; mb < 2; mb++)
                #pragma unroll
                for (int nt = 0; nt < 8; nt++)
                    #pragma unroll
                    for (int r = 0; r < 4; r++) acc[mb][nt][r] = 0.0f;

            warp_gemm<4, STR2>(a1H, a1L,
                               smb + OFF_W2H + nh * 64 * STR2 * 2,
                               smb + OFF_W2L + nh * 64 * STR2 * 2,
                               lane, acc);

            // epilogue: bias + relu + hi/lo pack into A2
            #pragma unroll
            for (int nt = 0; nt < 8; nt++) {
                int col = nh * 64 + nt * 8 + cbase;
                float bb0 = sb2[col], bb1 = sb2[col + 1];
                #pragma unroll
                for (int mb = 0; mb < 2; mb++) {
                    #pragma unroll
                    for (int rp = 0; rp < 2; rp++) {
                        int row = mb * 16 + g + rp * 8;
                        float v0 = fmaxf(acc[mb][nt][2*rp]     + bb0, 0.0f);
                        float v1 = fmaxf(acc[mb][nt][2*rp + 1] + bb1, 0.0f);
                        float h0 = __half2float(__float2half_rn(v0));
                        float h1v = __half2float(__float2half_rn(v1));
                        uint32_t off = (uint32_t)(row * STR3 + col) * 2;
                        *(uint32_t*)(sm + (a2H - smb) + off) = pack2(v0, v1);
                        *(uint32_t*)(sm + (a2L - smb) + off) = pack2(v0 - h0, v1 - h1v);
                    }
                }
            }
        }
        __syncwarp();

        // per-row scatter bases (rows g, g+8, g+16, g+24 of this strip)
        int base_r[4];
        #pragma unroll
        for (int q = 0; q < 4; q++)
            base_r[q] = __shfl_sync(0xffffffffu, base, g + q * 8);

        // ---- layer 3: [32 x 128] x [128 x 128]^T + scatter-max ----
        #pragma unroll
        for (int nh = 0; nh < 2; nh++) {
            float acc[2][8][4];
            #pragma unroll
            for (int mb = 0; mb < 2; mb++)
                #pragma unroll
                for (int nt = 0; nt < 8; nt++)
                    #pragma unroll
                    for (int r = 0; r < 4; r++) acc[mb][nt][r] = 0.0f;

            warp_gemm<8, STR3>(a2H, a2L,
                               smb + OFF_W3H + nh * 64 * STR3 * 2,
                               smb + OFF_W3L + nh * 64 * STR3 * 2,
                               lane, acc);

            #pragma unroll
            for (int nt = 0; nt < 8; nt++) {
                int col = nh * 64 + nt * 8 + cbase;
                float bb0 = sb3[col], bb1 = sb3[col + 1];
                int* o0 = iout + col * HW;
                int* o1 = iout + (col + 1) * HW;
                #pragma unroll
                for (int mb = 0; mb < 2; mb++) {
                    #pragma unroll
                    for (int rp = 0; rp < 2; rp++) {
                        int bse = base_r[mb * 2 + rp];
                        if (bse >= 0) {
                            float v0 = fmaxf(acc[mb][nt][2*rp]     + bb0, 0.0f);
                            float v1 = fmaxf(acc[mb][nt][2*rp + 1] + bb1, 0.0f);
                            atomicMax(o0 + bse, __float_as_int(v0));
                            atomicMax(o1 + bse, __float_as_int(v1));
                        }
                    }
                }
            }
        }
        __syncwarp();
    }
}

extern "C" void kernel_launch(void* const* d_in, const int* in_sizes, int n_in,
                              void* d_out, int out_size)
{
    const float* points = (const float*)d_in[0];
    const float* W1  = (const float*)d_in[1];
    const float* b1  = (const float*)d_in[2];
    const float* g1  = (const float*)d_in[3];
    const float* be1 = (const float*)d_in[4];
    const float* m1  = (const float*)d_in[5];
    const float* v1  = (const float*)d_in[6];
    const float* W2  = (const float*)d_in[7];
    const float* b2  = (const float*)d_in[8];
    const float* g2  = (const float*)d_in[9];
    const float* be2 = (const float*)d_in[10];
    const float* m2  = (const float*)d_in[11];
    const float* v2  = (const float*)d_in[12];
    const float* W3  = (const float*)d_in[13];
    const float* b3  = (const float*)d_in[14];
    const float* g3  = (const float*)d_in[15];
    const float* be3 = (const float*)d_in[16];
    const float* m3  = (const float*)d_in[17];
    const float* v3  = (const float*)d_in[18];

    cudaMemsetAsync(d_out, 0, (size_t)out_size * sizeof(float), 0);

    prep_kernel<<<64, 256>>>(W1, b1, g1, be1, m1, v1,
                             W2, b2, g2, be2, m2, v2,
                             W3, b3, g3, be3, m3, v3);

    cudaFuncSetAttribute(enc_kernel,
                         cudaFuncAttributeMaxDynamicSharedMemorySize, SMEM_SZ);
    enc_kernel<<<148, 128, SMEM_SZ>>>((const float4*)points, (float*)d_out);
}

// round 4
// speedup vs baseline: 2.5174x; 1.1505x over previous
#include <cuda_runtime.h>
#include <cuda_fp16.h>
#include <cstdint>

#define TOTAL_PTS 480000
#define NWTILES   15000        // 480000 / 32 points per warp-tile
#define HW        16384        // 128*128
#define EPSF      1e-5f
#define STR2      72           // K=64  + 8 halfs pad
#define STR3      136          // K=128 + 8 halfs pad

// ---------------- warp MMA helpers (sm_80+; safe on sm_103 base target) -------
__device__ __forceinline__ uint32_t smem_u32(const void* p){
    uint32_t a;
    asm("{ .reg .u64 t; cvta.to.shared.u64 t, %1; cvt.u32.u64 %0, t; }" : "=r"(a) : "l"(p));
    return a;
}
__device__ __forceinline__ void ldsm4(uint32_t r[4], uint32_t addr){
    asm volatile("ldmatrix.sync.aligned.m8n8.x4.shared.b16 {%0,%1,%2,%3}, [%4];"
        : "=r"(r[0]), "=r"(r[1]), "=r"(r[2]), "=r"(r[3]) : "r"(addr));
}
__device__ __forceinline__ void mma16816(float (&d)[4], const uint32_t (&a)[4], uint32_t b0, uint32_t b1){
    asm volatile("mma.sync.aligned.m16n8k16.row.col.f32.f16.f16.f32 "
        "{%0,%1,%2,%3},{%4,%5,%6,%7},{%8,%9},{%0,%1,%2,%3};"
        : "+f"(d[0]), "+f"(d[1]), "+f"(d[2]), "+f"(d[3])
        : "r"(a[0]), "r"(a[1]), "r"(a[2]), "r"(a[3]), "r"(b0), "r"(b1));
}
__device__ __forceinline__ uint32_t pack2(float a, float b){
    __half2 h = __floats2half2_rn(a, b);
    return *reinterpret_cast<uint32_t*>(&h);
}
__device__ __forceinline__ void hilo(float v0, float v1, uint32_t &hi, uint32_t &lo){
    __half h0 = __float2half_rn(v0), h1 = __float2half_rn(v1);
    __half2 hh = __halves2half2(h0, h1);
    hi = *reinterpret_cast<uint32_t*>(&hh);
    lo = pack2(v0 - __half2float(h0), v1 - __half2float(h1));
}

// ---------------- prepped globals (BN folded, hi/lo split, padded layout) -----
__device__ __align__(16) unsigned short g_w2hi[128*STR2];
__device__ __align__(16) unsigned short g_w2lo[128*STR2];
__device__ __align__(16) unsigned short g_w3hi[128*STR3];
__device__ __align__(16) unsigned short g_w3lo[128*STR3];
__device__ __align__(16) float g_w1f[256];
__device__ float g_b1f[64], g_b2f[128], g_b3f[128];

__global__ void prep_kernel(
    const float* __restrict__ W1, const float* __restrict__ b1,
    const float* __restrict__ g1, const float* __restrict__ be1,
    const float* __restrict__ m1, const float* __restrict__ v1,
    const float* __restrict__ W2, const float* __restrict__ b2,
    const float* __restrict__ g2, const float* __restrict__ be2,
    const float* __restrict__ m2, const float* __restrict__ v2,
    const float* __restrict__ W3, const float* __restrict__ b3,
    const float* __restrict__ g3, const float* __restrict__ be3,
    const float* __restrict__ m3, const float* __restrict__ v3)
{
    int idx = blockIdx.x * blockDim.x + threadIdx.x;
    int nthr = gridDim.x * blockDim.x;
    for (int i = idx; i < 8192; i += nthr) {           // W2 [128 n][64 k]
        int o = i >> 6, k = i & 63;
        float s = g2[o] * rsqrtf(v2[o] + EPSF);
        float w = W2[i] * s;
        float hi = __half2float(__float2half_rn(w));
        g_w2hi[o*STR2 + k] = __half_as_ushort(__float2half_rn(w));
        g_w2lo[o*STR2 + k] = __half_as_ushort(__float2half_rn(w - hi));
    }
    for (int i = idx; i < 16384; i += nthr) {          // W3 [128 n][128 k]
        int o = i >> 7, k = i & 127;
        float s = g3[o] * rsqrtf(v3[o] + EPSF);
        float w = W3[i] * s;
        float hi = __half2float(__float2half_rn(w));
        g_w3hi[o*STR3 + k] = __half_as_ushort(__float2half_rn(w));
        g_w3lo[o*STR3 + k] = __half_as_ushort(__float2half_rn(w - hi));
    }
    for (int i = idx; i < 256; i += nthr) { int o = i >> 2; g_w1f[i] = W1[i] * g1[o] * rsqrtf(v1[o] + EPSF); }
    for (int i = idx; i < 64; i += nthr)  { float s = g1[i]*rsqrtf(v1[i]+EPSF); g_b1f[i] = (b1[i]-m1[i])*s + be1[i]; }
    for (int i = idx; i < 128; i += nthr) { float s = g2[i]*rsqrtf(v2[i]+EPSF); g_b2f[i] = (b2[i]-m2[i])*s + be2[i]; }
    for (int i = idx; i < 128; i += nthr) { float s = g3[i]*rsqrtf(v3[i]+EPSF); g_b3f[i] = (b3[i]-m3[i])*s + be3[i]; }
}

// ---------------- smem layout (bytes): weights only ----------------
#define OFF_W2H  0
#define OFF_W2L  (OFF_W2H + 128*STR2*2)     // 18432
#define OFF_W3H  (OFF_W2L + 128*STR2*2)     // 36864
#define OFF_W3L  (OFF_W3H + 128*STR3*2)     // 71680
#define OFF_B1   (OFF_W3L + 128*STR3*2)     // 106496
#define OFF_B2   (OFF_B1 + 256)
#define OFF_B3   (OFF_B2 + 512)
#define OFF_W1   (OFF_B3 + 512)
#define SMEM_SZ  (OFF_W1 + 1024)            // 108800 -> 2 CTAs/SM

// layer-2 GEMM pass: A frags in regs, B via ldmatrix. acc[nh][mb][nt][4].
__device__ __forceinline__ void l2_pass(const uint32_t (&A)[4][2][4], uint32_t B,
                                        uint32_t boff, float (&acc)[2][2][8][4])
{
    #pragma unroll
    for (int ks = 0; ks < 4; ks++)
        #pragma unroll
        for (int nh = 0; nh < 2; nh++)
            #pragma unroll
            for (int ntp = 0; ntp < 4; ntp++) {
                uint32_t b[4];
                ldsm4(b, B + nh*(64*STR2*2) + boff + ks*32 + ntp*(16*STR2*2));
                mma16816(acc[nh][0][2*ntp],   A[ks][0], b[0], b[1]);
                mma16816(acc[nh][0][2*ntp+1], A[ks][0], b[2], b[3]);
                mma16816(acc[nh][1][2*ntp],   A[ks][1], b[0], b[1]);
                mma16816(acc[nh][1][2*ntp+1], A[ks][1], b[2], b[3]);
            }
}

// layer-3 GEMM pass for one 64-col n-half.
__device__ __forceinline__ void l3_pass(const uint32_t (&A)[8][2][4], uint32_t B,
                                        uint32_t boff, float (&acc)[2][8][4])
{
    #pragma unroll
    for (int ks = 0; ks < 8; ks++)
        #pragma unroll
        for (int ntp = 0; ntp < 4; ntp++) {
            uint32_t b[4];
            ldsm4(b, B + boff + ks*32 + ntp*(16*STR3*2));
            mma16816(acc[0][2*ntp],   A[ks][0], b[0], b[1]);
            mma16816(acc[0][2*ntp+1], A[ks][0], b[2], b[3]);
            mma16816(acc[1][2*ntp],   A[ks][1], b[0], b[1]);
            mma16816(acc[1][2*ntp+1], A[ks][1], b[2], b[3]);
        }
}

__global__ void __launch_bounds__(128, 2)
enc_kernel(const float4* __restrict__ pts, float* __restrict__ out)
{
    extern __shared__ __align__(16) char sm[];
    const uint32_t smb = smem_u32(sm);
    const int t = threadIdx.x, lane = t & 31, wid = t >> 5;
    int* iout = (int*)out;

    { // stage weights
        uint4* d; const uint4* s;
        d = (uint4*)(sm + OFF_W2H); s = (const uint4*)g_w2hi; for (int i = t; i < 128*STR2*2/16; i += 128) d[i] = s[i];
        d = (uint4*)(sm + OFF_W2L); s = (const uint4*)g_w2lo; for (int i = t; i < 128*STR2*2/16; i += 128) d[i] = s[i];
        d = (uint4*)(sm + OFF_W3H); s = (const uint4*)g_w3hi; for (int i = t; i < 128*STR3*2/16; i += 128) d[i] = s[i];
        d = (uint4*)(sm + OFF_W3L); s = (const uint4*)g_w3lo; for (int i = t; i < 128*STR3*2/16; i += 128) d[i] = s[i];
        float* f;
        f = (float*)(sm + OFF_W1); for (int i = t; i < 256; i += 128) f[i] = g_w1f[i];
        f = (float*)(sm + OFF_B1); if (t < 64)  f[t] = g_b1f[t];
        f = (float*)(sm + OFF_B2); if (t < 128) f[t] = g_b2f[t];
        f = (float*)(sm + OFF_B3); if (t < 128) f[t] = g_b3f[t];
    }
    __syncthreads();

    const float4* sW1 = (const float4*)(sm + OFF_W1);
    const float* sb1 = (const float*)(sm + OFF_B1);
    const float* sb2 = (const float*)(sm + OFF_B2);
    const float* sb3 = (const float*)(sm + OFF_B3);

    const int g = lane >> 2;
    const int cbase = (lane & 3) * 2;
    const uint32_t boff2 = (uint32_t)(((lane & 7) + ((lane >> 4) << 3)) * STR2) * 2 + (lane & 8) * 2;
    const uint32_t boff3 = (uint32_t)(((lane & 7) + ((lane >> 4) << 3)) * STR3) * 2 + (lane & 8) * 2;

    const int gwarp = blockIdx.x * 4 + wid;
    const int nwarps = gridDim.x * 4;

    for (int wt = gwarp; wt < NWTILES; wt += nwarps) {
        const int p = wt * 32 + lane;
        float4 pt = pts[p];

        float xn = (pt.x + 50.0f) / 100.0f;
        float yn = (pt.y + 50.0f) / 100.0f;
        bool valid = (xn >= 0.0f) && (xn <= 1.0f) && (yn >= 0.0f) && (yn <= 1.0f);
        int gx = min(max((int)(xn * 127.0f), 0), 127);
        int gy = min(max((int)(yn * 127.0f), 0), 127);
        int base = valid ? ((p / 120000) * (128 * HW) + gy * 128 + gx) : -1;

        // bases for the 4 rows this lane's accumulators cover (rows g+8q)
        int base_r[4];
        #pragma unroll
        for (int q = 0; q < 4; q++)
            base_r[q] = __shfl_sync(0xffffffffu, base, g + q * 8);

        // points for rows g+8q
        float4 ptq[4];
        #pragma unroll
        for (int q = 0; q < 4; q++) {
            int src = g + 8 * q;
            ptq[q].x = __shfl_sync(0xffffffffu, pt.x, src);
            ptq[q].y = __shfl_sync(0xffffffffu, pt.y, src);
            ptq[q].z = __shfl_sync(0xffffffffu, pt.z, src);
            ptq[q].w = __shfl_sync(0xffffffffu, pt.w, src);
        }

        // ---- layer 1: build A1 hi/lo fragments directly in registers ----
        uint32_t a1H[4][2][4], a1L[4][2][4];
        #pragma unroll
        for (int ks = 0; ks < 4; ks++)
            #pragma unroll
            for (int off8 = 0; off8 < 2; off8++) {
                int k0 = ks * 16 + off8 * 8 + cbase;
                float4 w0 = sW1[k0], w1 = sW1[k0 + 1];
                float bb0 = sb1[k0], bb1 = sb1[k0 + 1];
                #pragma unroll
                for (int mb = 0; mb < 2; mb++)
                    #pragma unroll
                    for (int rh = 0; rh < 2; rh++) {
                        float4 q = ptq[2 * mb + rh];
                        float v0 = bb0, v1 = bb1;
                        v0 = fmaf(q.x, w0.x, v0); v0 = fmaf(q.y, w0.y, v0);
                        v0 = fmaf(q.z, w0.z, v0); v0 = fmaf(q.w, w0.w, v0);
                        v1 = fmaf(q.x, w1.x, v1); v1 = fmaf(q.y, w1.y, v1);
                        v1 = fmaf(q.z, w1.z, v1); v1 = fmaf(q.w, w1.w, v1);
                        v0 = fmaxf(v0, 0.0f); v1 = fmaxf(v1, 0.0f);
                        hilo(v0, v1, a1H[ks][mb][off8 * 2 + rh], a1L[ks][mb][off8 * 2 + rh]);
                    }
            }

        // ---- layer 2: [32x64] x [64x128]^T, 3-pass hi/lo ----
        float acc2[2][2][8][4];
        #pragma unroll
        for (int nh = 0; nh < 2; nh++)
            #pragma unroll
            for (int mb = 0; mb < 2; mb++)
                #pragma unroll
                for (int nt = 0; nt < 8; nt++)
                    #pragma unroll
                    for (int r = 0; r < 4; r++) acc2[nh][mb][nt][r] = 0.0f;

        l2_pass(a1H, smb + OFF_W2H, boff2, acc2);
        l2_pass(a1L, smb + OFF_W2H, boff2, acc2);
        l2_pass(a1H, smb + OFF_W2L, boff2, acc2);

        // ---- epilogue 2: bias+relu, convert C frags -> layer-3 A frags ----
        uint32_t a2H[8][2][4], a2L[8][2][4];
        #pragma unroll
        for (int ks3 = 0; ks3 < 8; ks3++) {
            const int nh = ks3 >> 2;
            const int ntA = (ks3 & 3) * 2;
            const int colA = ks3 * 16 + cbase;
            float bA0 = sb2[colA], bA1 = sb2[colA + 1];
            float bB0 = sb2[colA + 8], bB1 = sb2[colA + 9];
            #pragma unroll
            for (int mb = 0; mb < 2; mb++) {
                hilo(fmaxf(acc2[nh][mb][ntA][0] + bA0, 0.0f),
                     fmaxf(acc2[nh][mb][ntA][1] + bA1, 0.0f),
                     a2H[ks3][mb][0], a2L[ks3][mb][0]);
                hilo(fmaxf(acc2[nh][mb][ntA][2] + bA0, 0.0f),
                     fmaxf(acc2[nh][mb][ntA][3] + bA1, 0.0f),
                     a2H[ks3][mb][1], a2L[ks3][mb][1]);
                hilo(fmaxf(acc2[nh][mb][ntA + 1][0] + bB0, 0.0f),
                     fmaxf(acc2[nh][mb][ntA + 1][1] + bB1, 0.0f),
                     a2H[ks3][mb][2], a2L[ks3][mb][2]);
                hilo(fmaxf(acc2[nh][mb][ntA + 1][2] + bB0, 0.0f),
                     fmaxf(acc2[nh][mb][ntA + 1][3] + bB1, 0.0f),
                     a2H[ks3][mb][3], a2L[ks3][mb][3]);
            }
        }

        // ---- layer 3: [32x128] x [128x128]^T + scatter-max ----
        #pragma unroll
        for (int nh3 = 0; nh3 < 2; nh3++) {
            float acc3[2][8][4];
            #pragma unroll
            for (int mb = 0; mb < 2; mb++)
                #pragma unroll
                for (int nt = 0; nt < 8; nt++)
                    #pragma unroll
                    for (int r = 0; r < 4; r++) acc3[mb][nt][r] = 0.0f;

            const uint32_t bh = smb + OFF_W3H + nh3 * (64 * STR3 * 2);
            const uint32_t bl = smb + OFF_W3L + nh3 * (64 * STR3 * 2);
            l3_pass(a2H, bh, boff3, acc3);
            l3_pass(a2L, bh, boff3, acc3);
            l3_pass(a2H, bl, boff3, acc3);

            #pragma unroll
            for (int nt = 0; nt < 8; nt++) {
                int col = nh3 * 64 + nt * 8 + cbase;
                float bb0 = sb3[col], bb1 = sb3[col + 1];
                int* o0 = iout + col * HW;
                int* o1 = iout + (col + 1) * HW;
                #pragma unroll
                for (int mb = 0; mb < 2; mb++)
                    #pragma unroll
                    for (int rp = 0; rp < 2; rp++) {
                        int bse = base_r[mb * 2 + rp];
                        if (bse >= 0) {
                            float v0 = fmaxf(acc3[mb][nt][2 * rp]     + bb0, 0.0f);
                            float v1 = fmaxf(acc3[mb][nt][2 * rp + 1] + bb1, 0.0f);
                            atomicMax(o0 + bse, __float_as_int(v0));
                            atomicMax(o1 + bse, __float_as_int(v1));
                        }
                    }
            }
        }
    }
}

extern "C" void kernel_launch(void* const* d_in, const int* in_sizes, int n_in,
                              void* d_out, int out_size)
{
    const float* points = (const float*)d_in[0];
    const float* W1  = (const float*)d_in[1];
    const float* b1  = (const float*)d_in[2];
    const float* g1  = (const float*)d_in[3];
    const float* be1 = (const float*)d_in[4];
    const float* m1  = (const float*)d_in[5];
    const float* v1  = (const float*)d_in[6];
    const float* W2  = (const float*)d_in[7];
    const float* b2  = (const float*)d_in[8];
    const float* g2  = (const float*)d_in[9];
    const float* be2 = (const float*)d_in[10];
    const float* m2  = (const float*)d_in[11];
    const float* v2  = (const float*)d_in[12];
    const float* W3  = (const float*)d_in[13];
    const float* b3  = (const float*)d_in[14];
    const float* g3  = (const float*)d_in[15];
    const float* be3 = (const float*)d_in[16];
    const float* m3  = (const float*)d_in[17];
    const float* v3  = (const float*)d_in[18];

    cudaMemsetAsync(d_out, 0, (size_t)out_size * sizeof(float), 0);

    prep_kernel<<<64, 256>>>(W1, b1, g1, be1, m1, v1,
                             W2, b2, g2, be2, m2, v2,
                             W3, b3, g3, be3, m3, v3);

    cudaFuncSetAttribute(enc_kernel,
                         cudaFuncAttributeMaxDynamicSharedMemorySize, SMEM_SZ);
    enc_kernel<<<296, 128, SMEM_SZ>>>((const float4*)points, (float*)d_out);
}